// round 6
// baseline (speedup 1.0000x reference)
#include <cuda_runtime.h>

#define VOCAB 500
#define EMB   64
#define HID   64
#define BATCH 512
#define SEQ   512
#define ROWS_PER_CTA 4   // 2 groups x 2 interleaved rows per thread

// Precomputed input projection: E'[v][i] = b_ih0[i] + sum_j emb[v][j]*W_ih0[i][j]
__device__ float g_xproj[VOCAB * HID];

typedef unsigned long long u64;

__device__ __forceinline__ void fma2(u64 &d, u64 a, u64 b) {
    asm("fma.rn.f32x2 %0, %1, %2, %0;" : "+l"(d) : "l"(a), "l"(b));
}
__device__ __forceinline__ u64 add2(u64 a, u64 b) {
    u64 r; asm("add.rn.f32x2 %0, %1, %2;" : "=l"(r) : "l"(a), "l"(b)); return r;
}
__device__ __forceinline__ float hsum2(u64 a, u64 b) {
    u64 s = add2(a, b);
    float lo, hi;
    asm("mov.b64 {%0,%1}, %2;" : "=f"(lo), "=f"(hi) : "l"(s));
    return lo + hi;
}
__device__ __forceinline__ float fast_tanh(float x) {
    float e = __expf(2.0f * x);
    return 1.0f - __fdividef(2.0f, e + 1.0f);
}

// ---------------------------------------------------------------------------
// Kernel 1: fold embedding + layer-0 input projection into a 500x64 LUT.
// ---------------------------------------------------------------------------
__global__ void xproj_kernel(const float* __restrict__ emb,
                             const float* __restrict__ W_ih0,
                             const float* __restrict__ b_ih0) {
    __shared__ float se[EMB];
    const int v = blockIdx.x;
    const int i = threadIdx.x;
    se[i] = emb[v * EMB + i];
    __syncthreads();
    float acc = 0.0f;
    const float4* wr = (const float4*)(W_ih0 + i * EMB);
    #pragma unroll
    for (int q = 0; q < 16; q++) {
        float4 wv = __ldg(wr + q);
        acc += wv.x * se[4*q+0] + wv.y * se[4*q+1] + wv.z * se[4*q+2] + wv.w * se[4*q+3];
    }
    g_xproj[v * HID + i] = acc + b_ih0[i];
}

// ---------------------------------------------------------------------------
// Kernel 2: sequential scan. CTA = 128 threads = 2 groups x 64; grid = 128
// (1 CTA/SM, 1 warp per SMSP). Thread (g, i) holds weight row i of all three
// matrices (192 regs) and processes TWO interleaved batch rows — weights are
// row-independent, so the second stream is register-free and its arithmetic
// hides the first stream's barrier/LDS/MUFU latency. 2 barriers per step,
// each amortized over 2 rows.
// Index dtype (int64 vs int32) detected from the GLOBAL first 128 words —
// in-bounds for either layout (int32 buffer has NTOK=262144 words). If the
// buffer is int64 (LE), every odd word of the first 64 tokens is zero; for
// int32, 64 consecutive tokens all zero has probability (1/500)^64 ~ 0.
// ---------------------------------------------------------------------------
__global__ void __launch_bounds__(128, 1)
scan_kernel(const int* __restrict__ xw,
            const float* __restrict__ W_hh0,
            const float* __restrict__ b_hh0,
            const float* __restrict__ W_ih1,
            const float* __restrict__ W_hh1,
            const float* __restrict__ b_ih1,
            const float* __restrict__ b_hh1,
            const float* __restrict__ fc_w,
            const float* __restrict__ fc_b,
            float* __restrict__ out) {
    __shared__ __align__(16) float sh1[ROWS_PER_CTA][HID];
    __shared__ __align__(16) float sh2[ROWS_PER_CTA][HID];
    __shared__ int   sidx[ROWS_PER_CTA * SEQ];
    __shared__ float swsum[ROWS_PER_CTA][2];
    __shared__ int   s_is64;

    const int tid  = threadIdx.x;
    const int g    = tid >> 6;          // group 0/1
    const int i    = tid & 63;          // owned output row of W
    const int lane = tid & 31;
    const int half = (tid >> 5) & 1;    // warp within group
    const int rbase = blockIdx.x * ROWS_PER_CTA;
    const int L0 = g * 2, L1 = g * 2 + 1;        // local rows for this thread

    // --- weights: full row i of each matrix, as f32x2 pairs (192 regs) ---
    u64 w0[32], w1[32], w2[32];         // W_hh0, W_ih1, W_hh1
    {
        const u64* q0 = (const u64*)(W_hh0 + i * HID);
        const u64* q1 = (const u64*)(W_ih1 + i * HID);
        const u64* q2 = (const u64*)(W_hh1 + i * HID);
        #pragma unroll
        for (int q = 0; q < 32; q++) {
            w0[q] = __ldg(q0 + q);
            w1[q] = __ldg(q1 + q);
            w2[q] = __ldg(q2 + q);
        }
    }
    const float bia1 = b_hh0[i];
    const float bia2 = b_ih1[i] + b_hh1[i];

    // --- detect index dtype from the GLOBAL first 128 words (in-bounds for
    //     both layouts, identical verdict in every CTA), then stage+convert ---
    if (tid == 0) {
        int z = 0;
        #pragma unroll
        for (int k = 1; k < 128; k += 2) z |= xw[k];
        s_is64 = (z == 0);
    }
    __syncthreads();
    {
        const int is64 = s_is64;
        const int base = rbase * SEQ;
        for (int k = tid; k < ROWS_PER_CTA * SEQ; k += 128) {
            int v = is64 ? xw[2 * (base + k)] : xw[base + k];
            sidx[k] = min(max(v, 0), VOCAB - 1);
        }
    }
    __syncthreads();

    const int* ixA = sidx + L0 * SEQ;
    const int* ixB = sidx + L1 * SEQ;
    const ulonglong2* H1a = (const ulonglong2*)sh1[L0];
    const ulonglong2* H1b = (const ulonglong2*)sh1[L1];
    const ulonglong2* H2a = (const ulonglong2*)sh2[L0];
    const ulonglong2* H2b = (const ulonglong2*)sh2[L1];

    // carried state per row-stream (h[-1] = 0)
    float cqA = 0.0f, crA = 0.0f, cqB = 0.0f, crB = 0.0f;
    float xnA = __ldg(&g_xproj[ixA[0] * HID + i]);
    float xnB = __ldg(&g_xproj[ixB[0] * HID + i]);
    float h2A = 0.0f, h2B = 0.0f;

    #pragma unroll 1
    for (int t = 0; t < SEQ; t++) {
        const float xcA = xnA, xcB = xnB;
        const int tn = (t + 1 < SEQ) ? (t + 1) : (SEQ - 1);
        xnA = __ldg(&g_xproj[ixA[tn] * HID + i]);
        xnB = __ldg(&g_xproj[ixB[tn] * HID + i]);

        // h1_new = tanh(Whh0.h1_prev + x_t + b1)   (both streams)
        const float h1A = fast_tanh(cqA + xcA + bia1);
        const float h1B = fast_tanh(cqB + xcB + bia1);
        sh1[L0][i] = h1A;
        sh1[L1][i] = h1B;
        __syncthreads();   // B1: h1_new visible

        // one pass over h1_new feeds BOTH Wih1 (this step) and Whh0 (next);
        // 8 independent fma chains (2 streams x 4) for latency hiding.
        u64 sA0 = 0, sA1 = 0, qA0 = 0, qA1 = 0;
        u64 sB0 = 0, sB1 = 0, qB0 = 0, qB1 = 0;
        #pragma unroll
        for (int m = 0; m < 16; m++) {
            ulonglong2 ha = H1a[m];
            fma2(sA0, w1[2*m],   ha.x); fma2(sA1, w1[2*m+1], ha.y);
            fma2(qA0, w0[2*m],   ha.x); fma2(qA1, w0[2*m+1], ha.y);
            ulonglong2 hb = H1b[m];
            fma2(sB0, w1[2*m],   hb.x); fma2(sB1, w1[2*m+1], hb.y);
            fma2(qB0, w0[2*m],   hb.x); fma2(qB1, w0[2*m+1], hb.y);
        }
        const float sA = hsum2(sA0, sA1);
        const float sB = hsum2(sB0, sB1);
        cqA = hsum2(qA0, qA1);
        cqB = hsum2(qB0, qB1);

        // h2_new = tanh(Wih1.h1_new + Whh1.h2_prev + b2)
        h2A = fast_tanh(sA + crA + bia2);
        h2B = fast_tanh(sB + crB + bia2);
        sh2[L0][i] = h2A;
        sh2[L1][i] = h2B;
        __syncthreads();   // B2: h2_new visible

        // recurrent term for next step: Whh1 . h2_new   (4 chains)
        u64 rA0 = 0, rA1 = 0, rB0 = 0, rB1 = 0;
        #pragma unroll
        for (int m = 0; m < 16; m++) {
            ulonglong2 ga = H2a[m];
            fma2(rA0, w2[2*m], ga.x); fma2(rA1, w2[2*m+1], ga.y);
            ulonglong2 gb = H2b[m];
            fma2(rB0, w2[2*m], gb.x); fma2(rB1, w2[2*m+1], gb.y);
        }
        crA = hsum2(rA0, rA1);
        crB = hsum2(rB0, rB1);
    }

    // --- final projection: out[b] = fc_w . h2 + fc_b ---
    const float fw = __ldg(&fc_w[i]);
    float vA = fw * h2A, vB = fw * h2B;
    #pragma unroll
    for (int off = 16; off; off >>= 1) {
        vA += __shfl_xor_sync(0xffffffffu, vA, off);
        vB += __shfl_xor_sync(0xffffffffu, vB, off);
    }
    if (lane == 0) { swsum[L0][half] = vA; swsum[L1][half] = vB; }
    __syncthreads();
    if (tid < ROWS_PER_CTA)
        out[rbase + tid] = swsum[tid][0] + swsum[tid][1] + fc_b[0];
}

// ---------------------------------------------------------------------------
extern "C" void kernel_launch(void* const* d_in, const int* in_sizes, int n_in,
                              void* d_out, int out_size) {
    const int*   x_raw = (const int*)d_in[0];
    const float* emb   = (const float*)d_in[1];
    const float* W_ih0 = (const float*)d_in[2];
    const float* W_hh0 = (const float*)d_in[3];
    const float* b_ih0 = (const float*)d_in[4];
    const float* b_hh0 = (const float*)d_in[5];
    const float* W_ih1 = (const float*)d_in[6];
    const float* W_hh1 = (const float*)d_in[7];
    const float* b_ih1 = (const float*)d_in[8];
    const float* b_hh1 = (const float*)d_in[9];
    const float* fc_w  = (const float*)d_in[10];
    const float* fc_b  = (const float*)d_in[11];
    float*       out   = (float*)d_out;

    xproj_kernel<<<VOCAB, HID>>>(emb, W_ih0, b_ih0);
    scan_kernel<<<BATCH / ROWS_PER_CTA, 128>>>(
        x_raw, W_hh0, b_hh0, W_ih1, W_hh1, b_ih1, b_hh1, fc_w, fc_b, out);
}

// round 7
// speedup vs baseline: 1.5354x; 1.5354x over previous
#include <cuda_runtime.h>

#define VOCAB 500
#define EMB   64
#define HID   64
#define BATCH 512
#define SEQ   512
#define ROWS_PER_CTA 4

// Precomputed input projection: E'[v][i] = b_ih0[i] + sum_j emb[v][j]*W_ih0[i][j]
__device__ float g_xproj[VOCAB * HID];

typedef unsigned long long u64;

__device__ __forceinline__ void fma2(u64 &d, u64 a, u64 b) {
    asm("fma.rn.f32x2 %0, %1, %2, %0;" : "+l"(d) : "l"(a), "l"(b));
}
__device__ __forceinline__ u64 add2(u64 a, u64 b) {
    u64 r; asm("add.rn.f32x2 %0, %1, %2;" : "=l"(r) : "l"(a), "l"(b)); return r;
}
__device__ __forceinline__ float hsum2(u64 a, u64 b) {
    u64 s = add2(a, b);
    float lo, hi;
    asm("mov.b64 {%0,%1}, %2;" : "=f"(lo), "=f"(hi) : "l"(s));
    return lo + hi;
}
__device__ __forceinline__ float fast_tanh(float x) {
    float e = __expf(2.0f * x);
    return 1.0f - __fdividef(2.0f, e + 1.0f);
}
// Row-local barrier: syncs only the 64 threads (2 warps) of one row.
__device__ __forceinline__ void bar_row(int row) {
    asm volatile("bar.sync %0, 64;" :: "r"(row + 1) : "memory");
}

// ---------------------------------------------------------------------------
// Kernel 1: fold embedding + layer-0 input projection into a 500x64 LUT.
// ---------------------------------------------------------------------------
__global__ void xproj_kernel(const float* __restrict__ emb,
                             const float* __restrict__ W_ih0,
                             const float* __restrict__ b_ih0) {
    __shared__ float se[EMB];
    const int v = blockIdx.x;
    const int i = threadIdx.x;
    se[i] = emb[v * EMB + i];
    __syncthreads();
    float acc = 0.0f;
    const float4* wr = (const float4*)(W_ih0 + i * EMB);
    #pragma unroll
    for (int q = 0; q < 16; q++) {
        float4 wv = __ldg(wr + q);
        acc += wv.x * se[4*q+0] + wv.y * se[4*q+1] + wv.z * se[4*q+2] + wv.w * se[4*q+3];
    }
    g_xproj[v * HID + i] = acc + b_ih0[i];
}

// ---------------------------------------------------------------------------
// Kernel 2: sequential scan. CTA = 256 threads = 4 rows x 64; grid = 128
// (1 CTA/SM, 2 warps per SMSP). Thread owns output i of its row with the
// FULL j range; weight rows of all three matrices in 192 regs (~226 total,
// no spills). Per step ONE merged fma region computes Wih1*h1_t, Whh0*h1_t
// (next step's recurrent term) and Whh1*h2_{t-1} together — 6 independent
// fma2 chains, one LDS-latency exposure. h2 is double-buffered (its read
// and write share a barrier interval); h1 needs no double-buffer. Rows sync
// on NAMED 64-thread barriers so the 4 rows drift into complementary phases
// and hide each other's serial latency. Index dtype (int64 vs int32) is
// detected from the global first 128 words (in-bounds for both layouts).
// ---------------------------------------------------------------------------
__global__ void __launch_bounds__(64 * ROWS_PER_CTA, 1)
scan_kernel(const int* __restrict__ xw,
            const float* __restrict__ W_hh0,
            const float* __restrict__ b_hh0,
            const float* __restrict__ W_ih1,
            const float* __restrict__ W_hh1,
            const float* __restrict__ b_ih1,
            const float* __restrict__ b_hh1,
            const float* __restrict__ fc_w,
            const float* __restrict__ fc_b,
            float* __restrict__ out) {
    __shared__ __align__(16) float sh1[ROWS_PER_CTA][HID];
    __shared__ __align__(16) float sh2[2][ROWS_PER_CTA][HID];
    __shared__ int   sidx[ROWS_PER_CTA * SEQ];
    __shared__ float swsum[ROWS_PER_CTA][2];
    __shared__ int   s_is64;

    const int tid  = threadIdx.x;
    const int row  = tid >> 6;          // 0..3
    const int i    = tid & 63;          // owned output
    const int lane = tid & 31;
    const int half = (tid >> 5) & 1;    // warp within row
    const int rbase = blockIdx.x * ROWS_PER_CTA;

    // --- weights: full row i of each matrix, as f32x2 pairs (192 regs) ---
    u64 w0[32], w1[32], w2[32];         // W_hh0, W_ih1, W_hh1
    {
        const u64* q0 = (const u64*)(W_hh0 + i * HID);
        const u64* q1 = (const u64*)(W_ih1 + i * HID);
        const u64* q2 = (const u64*)(W_hh1 + i * HID);
        #pragma unroll
        for (int q = 0; q < 32; q++) {
            w0[q] = __ldg(q0 + q);
            w1[q] = __ldg(q1 + q);
            w2[q] = __ldg(q2 + q);
        }
    }
    const float bia1 = b_hh0[i];
    const float bia2 = b_ih1[i] + b_hh1[i];

    // --- dtype probe on GLOBAL first 128 words (valid for either layout) ---
    if (tid == 0) {
        int z = 0;
        #pragma unroll
        for (int k = 1; k < 128; k += 2) z |= xw[k];
        s_is64 = (z == 0);
    }
    // zero h2 double buffers (h1 is written before first read)
    sh2[0][row][i] = 0.0f;
    sh2[1][row][i] = 0.0f;
    __syncthreads();
    {
        const int is64 = s_is64;
        const int base = rbase * SEQ;
        for (int k = tid; k < ROWS_PER_CTA * SEQ; k += 64 * ROWS_PER_CTA) {
            int v = is64 ? xw[2 * (base + k)] : xw[base + k];
            sidx[k] = min(max(v, 0), VOCAB - 1);
        }
    }
    __syncthreads();

    const int* my_ix = sidx + row * SEQ;
    const ulonglong2* H1 = (const ulonglong2*)sh1[row];

    float cq  = 0.0f;                              // Whh0 . h1_prev
    float xn  = __ldg(&g_xproj[my_ix[0] * HID + i]);
    float h2n = 0.0f;

    #pragma unroll 1
    for (int t = 0; t < SEQ; t++) {
        const float xc = xn;
        const int tn = (t + 1 < SEQ) ? (t + 1) : (SEQ - 1);
        xn = __ldg(&g_xproj[my_ix[tn] * HID + i]);   // prefetch next input

        // h1_t = tanh(Whh0.h1_{t-1} + x_t + b1)
        const float h1n = fast_tanh(cq + xc + bia1);
        sh1[row][i] = h1n;
        bar_row(row);   // B1: h1_t visible to both warps of this row

        // merged region: s = Wih1.h1_t, q = Whh0.h1_t (next step),
        //                r = Whh1.h2_{t-1}   — 6 independent chains
        const ulonglong2* H2 = (const ulonglong2*)sh2[t & 1][row];
        u64 s0 = 0, s1 = 0, q0 = 0, q1v = 0, r0 = 0, r1 = 0;
        #pragma unroll
        for (int m = 0; m < 16; m++) {
            ulonglong2 ha = H1[m];
            fma2(s0,  w1[2*m],   ha.x); fma2(s1,  w1[2*m+1], ha.y);
            fma2(q0,  w0[2*m],   ha.x); fma2(q1v, w0[2*m+1], ha.y);
            ulonglong2 ga = H2[m];
            fma2(r0,  w2[2*m],   ga.x); fma2(r1,  w2[2*m+1], ga.y);
        }
        cq = hsum2(q0, q1v);
        const float s = hsum2(s0, s1);
        const float r = hsum2(r0, r1);

        // h2_t = tanh(Wih1.h1_t + Whh1.h2_{t-1} + b2) -> opposite buffer
        h2n = fast_tanh(s + r + bia2);
        sh2[(t + 1) & 1][row][i] = h2n;
        bar_row(row);   // B2: h2_t visible
    }

    // --- final projection: out[b] = fc_w . h2 + fc_b ---
    float val = __ldg(&fc_w[i]) * h2n;
    #pragma unroll
    for (int off = 16; off; off >>= 1)
        val += __shfl_xor_sync(0xffffffffu, val, off);
    if (lane == 0) swsum[row][half] = val;
    bar_row(row);
    if (i == 0) out[rbase + row] = swsum[row][0] + swsum[row][1] + fc_b[0];
}

// ---------------------------------------------------------------------------
extern "C" void kernel_launch(void* const* d_in, const int* in_sizes, int n_in,
                              void* d_out, int out_size) {
    const int*   x_raw = (const int*)d_in[0];
    const float* emb   = (const float*)d_in[1];
    const float* W_ih0 = (const float*)d_in[2];
    const float* W_hh0 = (const float*)d_in[3];
    const float* b_ih0 = (const float*)d_in[4];
    const float* b_hh0 = (const float*)d_in[5];
    const float* W_ih1 = (const float*)d_in[6];
    const float* W_hh1 = (const float*)d_in[7];
    const float* b_ih1 = (const float*)d_in[8];
    const float* b_hh1 = (const float*)d_in[9];
    const float* fc_w  = (const float*)d_in[10];
    const float* fc_b  = (const float*)d_in[11];
    float*       out   = (float*)d_out;

    xproj_kernel<<<VOCAB, HID>>>(emb, W_ih0, b_ih0);
    scan_kernel<<<BATCH / ROWS_PER_CTA, 64 * ROWS_PER_CTA>>>(
        x_raw, W_hh0, b_hh0, W_ih1, W_hh1, b_ih1, b_hh1, fc_w, fc_b, out);
}